// round 5
// baseline (speedup 1.0000x reference)
#include <cuda_runtime.h>
#include <math.h>

// Problem constants
#define BB 2
#define NN 2048
#define BN 4096          // B*N
#define CC 256
#define HI 64
#define WI 176
#define HW (HI*WI)       // 11264
#define TS 16            // tile size
#define TBX (WI/TS)      // 11
#define TBY (HI/TS)      // 4
#define TPB (TBX*TBY)    // 44 tiles per batch
#define NT (BB*TPB)      // 88 tiles total
#define MAXG 2048        // max gaussians per tile (= N)
#define FM_SIZE (BB*CC*HW)

// ---------------- device scratch ----------------
__device__ float g_h1[BN*64];
__device__ float g_h2[BN*128];
__device__ float g_feats[BN*CC];
__device__ float g_ft1[BN*CC];
__device__ float g_featsT[BN*CC];

__device__ float g_px[BN], g_py[BN], g_isx[BN], g_isy[BN], g_w[BN], g_as[BN];
__device__ int   g_tcount[NT];
__device__ int   g_tlist[NT*MAXG];
__device__ float g_dens[BB*HW];
__device__ float g_unc [BB*HW];

// ---------------- projection + zero counters ----------------
__global__ void proj_kernel(const float* __restrict__ g, const float* __restrict__ Kin) {
    int i = blockIdx.x * blockDim.x + threadIdx.x;
    if (i < NT) g_tcount[i] = 0;
    if (i >= BN) return;
    const float* gd = g + (size_t)i * 14;
    float x = gd[0], y = gd[1], z = gd[2];
    float k00 = Kin[0], k01 = Kin[1], k02 = Kin[2];
    float k10 = Kin[3], k11 = Kin[4], k12 = Kin[5];
    float k20 = Kin[6], k21 = Kin[7], k22 = Kin[8];
    float pz = k20 * x + k21 * y + k22 * z;
    float denom = pz + 1e-6f;
    float pxn = (k00 * x + k01 * y + k02 * z) / denom;
    float pyn = (k10 * x + k11 * y + k12 * z) / denom;
    float scale_x = (float)WI / k02 * 0.5f;
    float scale_y = (float)HI / k12 * 0.5f;
    float px = pxn * scale_x;
    float py = pyn * scale_y;
    bool valid = (z > 0.1f);
    bool inb = (px >= 0.f) && (px < (float)WI) && (py >= 0.f) && (py < (float)HI);
    bool mask = valid && inb;
    float sx = fmaxf(gd[5] * scale_x, 1.0f);
    float sy = fmaxf(gd[6] * scale_y, 1.0f);
    g_px[i] = px;  g_py[i] = py;
    g_isx[i] = 1.0f / sx;  g_isy[i] = 1.0f / sy;
    g_w[i]  = mask ? gd[12] : 0.0f;
    g_as[i] = 0.5f * (sx + sy);
}

// ---------------- binning ----------------
__global__ void bin_kernel() {
    int i = blockIdx.x * blockDim.x + threadIdx.x;
    if (i >= BN) return;
    if (g_w[i] == 0.0f) return;
    float px = g_px[i], py = g_py[i];
    float rx = 3.0f / g_isx[i];
    float ry = 3.0f / g_isy[i];
    int b = i >> 11;  // / NN
    int tx0 = max(0, (int)floorf((px - rx) * (1.0f / TS)));
    int tx1 = min(TBX - 1, (int)floorf((px + rx) * (1.0f / TS)));
    int ty0 = max(0, (int)floorf((py - ry) * (1.0f / TS)));
    int ty1 = min(TBY - 1, (int)floorf((py + ry) * (1.0f / TS)));
    for (int ty = ty0; ty <= ty1; ty++)
        for (int tx = tx0; tx <= tx1; tx++) {
            int t = b * TPB + ty * TBX + tx;
            int o = atomicAdd(&g_tcount[t], 1);
            if (o < MAXG) g_tlist[t * MAXG + o] = i;
        }
}

// ---------------- generic fp32 GEMM: C = act(A[MxK] @ W[KxN] + b) ----------------
// TILE_M=64, TILE_N=64, TILE_K=16, 256 threads, 4x4 microtile.
__global__ void __launch_bounds__(256) gemm_kernel(
    const float* __restrict__ A, const float* __restrict__ Wm,
    const float* __restrict__ bias, float* __restrict__ Cm,
    int M, int Kd, int Nd, int doRelu)
{
    __shared__ float As[16][65];
    __shared__ float Bs[16][64];
    int m0 = blockIdx.x * 64;
    int n0 = blockIdx.y * 64;
    int t = threadIdx.x;
    int txq = t & 15;       // 0..15 -> N groups of 4
    int tyq = t >> 4;       // 0..15 -> M groups of 4
    float acc[4][4];
    #pragma unroll
    for (int i = 0; i < 4; i++)
        #pragma unroll
        for (int j = 0; j < 4; j++) acc[i][j] = 0.f;

    for (int k0 = 0; k0 < Kd; k0 += 16) {
        // load A tile (64 x 16), transposed into As[k][m]
        {
            int r = t >> 4, c = t & 15;
            #pragma unroll
            for (int it = 0; it < 4; it++) {
                int m = m0 + r + it * 16;
                int k = k0 + c;
                As[c][r + it * 16] = (k < Kd) ? A[(size_t)m * Kd + k] : 0.f;
            }
        }
        // load W tile (16 x 64)
        {
            int kk = t >> 6, j = t & 63;
            #pragma unroll
            for (int it = 0; it < 4; it++) {
                int k = k0 + kk + it * 4;
                Bs[kk + it * 4][j] = (k < Kd) ? Wm[(size_t)k * Nd + n0 + j] : 0.f;
            }
        }
        __syncthreads();
        #pragma unroll
        for (int kk = 0; kk < 16; kk++) {
            float a0 = As[kk][tyq * 4 + 0];
            float a1 = As[kk][tyq * 4 + 1];
            float a2 = As[kk][tyq * 4 + 2];
            float a3 = As[kk][tyq * 4 + 3];
            float4 bq = *(const float4*)&Bs[kk][txq * 4];
            acc[0][0] += a0 * bq.x; acc[0][1] += a0 * bq.y; acc[0][2] += a0 * bq.z; acc[0][3] += a0 * bq.w;
            acc[1][0] += a1 * bq.x; acc[1][1] += a1 * bq.y; acc[1][2] += a1 * bq.z; acc[1][3] += a1 * bq.w;
            acc[2][0] += a2 * bq.x; acc[2][1] += a2 * bq.y; acc[2][2] += a2 * bq.z; acc[2][3] += a2 * bq.w;
            acc[3][0] += a3 * bq.x; acc[3][1] += a3 * bq.y; acc[3][2] += a3 * bq.z; acc[3][3] += a3 * bq.w;
        }
        __syncthreads();
    }
    float4 bv = *(const float4*)&bias[n0 + txq * 4];
    #pragma unroll
    for (int i = 0; i < 4; i++) {
        float4 o;
        o.x = acc[i][0] + bv.x; o.y = acc[i][1] + bv.y;
        o.z = acc[i][2] + bv.z; o.w = acc[i][3] + bv.w;
        if (doRelu) {
            o.x = fmaxf(o.x, 0.f); o.y = fmaxf(o.y, 0.f);
            o.z = fmaxf(o.z, 0.f); o.w = fmaxf(o.w, 0.f);
        }
        *(float4*)&Cm[(size_t)(m0 + tyq * 4 + i) * Nd + n0 + txq * 4] = o;
    }
}

// ---------------- tile render ----------------
// grid: (NT, 4 channel slices), 256 threads.
// Each block: one 16x16 pixel tile, 64 channels. Accumulators in registers:
// thread owns pixel row ly (its 16 pixels) x 4 channels -> acc[4][16].
__global__ void __launch_bounds__(256, 2) render_kernel(float* __restrict__ out_fm) {
    int tile = blockIdx.x;         // 0..NT-1
    int slice = blockIdx.y;        // 0..3
    int b = tile / TPB;
    int tl = tile % TPB;
    int tx0 = (tl % TBX) * TS;
    int ty0 = (tl / TBX) * TS;
    int t = threadIdx.x;
    int lx = t & 15;
    int ly = t >> 4;

    __shared__ float s_px[16], s_py[16], s_isx[16], s_isy[16], s_w[16], s_as[16];
    __shared__ int   s_n[16];
    __shared__ float s_ex[16][16], s_ey[16][16], s_dx2[16][16], s_dy2[16][16];
    __shared__ float s_gw[16][256];
    __shared__ float s_F[16][64];

    float acc[4][16];
    #pragma unroll
    for (int i = 0; i < 4; i++)
        #pragma unroll
        for (int p = 0; p < 16; p++) acc[i][p] = 0.f;
    float dacc = 0.f, uacc = 0.f;

    int K = g_tcount[tile];
    if (K > MAXG) K = MAXG;

    for (int c0 = 0; c0 < K; c0 += 16) {
        // load params for up to 16 gaussians
        if (t < 16) {
            int idx = c0 + t;
            if (idx < K) {
                int n = g_tlist[tile * MAXG + idx];
                s_n[t] = n;
                s_px[t] = g_px[n];  s_py[t] = g_py[n];
                s_isx[t] = g_isx[n]; s_isy[t] = g_isy[n];
                s_w[t] = g_w[n];   s_as[t] = g_as[n];
            } else {
                s_n[t] = 0;
                s_px[t] = 3e8f; s_py[t] = 3e8f;
                s_isx[t] = 1.f; s_isy[t] = 1.f;
                s_w[t] = 0.f;  s_as[t] = 0.f;
            }
        }
        __syncthreads();
        // load feats slice: 16 gaussians x 64 channels
        {
            int j = t >> 4;
            int cc = (t & 15) * 4;
            int n = s_n[j];
            float4 f = *(const float4*)&g_featsT[(size_t)n * CC + slice * 64 + cc];
            *(float4*)&s_F[j][cc] = f;
        }
        // separable exp: thread (j = t/16, i2 = t%16)
        {
            int j = t >> 4, i2 = t & 15;
            float dx = ((float)(tx0 + i2) - s_px[j]) * s_isx[j];
            float dx2 = dx * dx;
            s_dx2[j][i2] = dx2;
            s_ex[j][i2] = __expf(-0.5f * dx2);
            float dy = ((float)(ty0 + i2) - s_py[j]) * s_isy[j];
            float dy2 = dy * dy;
            s_dy2[j][i2] = dy2;
            s_ey[j][i2] = __expf(-0.5f * dy2);
        }
        __syncthreads();
        // gw for my pixel (lx, ly) across 16 gaussians
        #pragma unroll
        for (int j = 0; j < 16; j++) {
            float d = s_dx2[j][lx] + s_dy2[j][ly];
            float gw = (d < 9.0f) ? s_w[j] * s_ex[j][lx] * s_ey[j][ly] : 0.0f;
            s_gw[j][t] = gw;
            if (slice == 0) { dacc += gw; uacc += gw * s_as[j]; }
        }
        __syncthreads();
        // GEMM: acc[ci][pp] += F[j][cg*4+ci] * gw[j][ly*16+pp]
        {
            int cg = lx;
            #pragma unroll
            for (int j = 0; j < 16; j++) {
                float4 f = *(const float4*)&s_F[j][cg * 4];
                const float* gwr = &s_gw[j][ly * 16];
                #pragma unroll
                for (int pp = 0; pp < 16; pp += 4) {
                    float4 g4 = *(const float4*)&gwr[pp];
                    acc[0][pp + 0] += f.x * g4.x; acc[0][pp + 1] += f.x * g4.y;
                    acc[0][pp + 2] += f.x * g4.z; acc[0][pp + 3] += f.x * g4.w;
                    acc[1][pp + 0] += f.y * g4.x; acc[1][pp + 1] += f.y * g4.y;
                    acc[1][pp + 2] += f.y * g4.z; acc[1][pp + 3] += f.y * g4.w;
                    acc[2][pp + 0] += f.z * g4.x; acc[2][pp + 1] += f.z * g4.y;
                    acc[2][pp + 2] += f.z * g4.z; acc[2][pp + 3] += f.z * g4.w;
                    acc[3][pp + 0] += f.w * g4.x; acc[3][pp + 1] += f.w * g4.y;
                    acc[3][pp + 2] += f.w * g4.z; acc[3][pp + 3] += f.w * g4.w;
                }
            }
        }
        __syncthreads();
    }

    // write feature sums: thread owns pixel row gy = ty0+ly, channels slice*64+lx*4 .. +3
    int gy = ty0 + ly;
    float* base = out_fm + (((size_t)(b * CC + slice * 64 + lx * 4) * HI + gy) * WI + tx0);
    #pragma unroll
    for (int ci = 0; ci < 4; ci++) {
        float* row = base + (size_t)ci * HW;
        #pragma unroll
        for (int pp = 0; pp < 16; pp += 4) {
            float4 o = make_float4(acc[ci][pp], acc[ci][pp + 1], acc[ci][pp + 2], acc[ci][pp + 3]);
            *(float4*)&row[pp] = o;
        }
    }
    if (slice == 0) {
        int pix = (ty0 + ly) * WI + tx0 + lx;
        g_dens[b * HW + pix] = dacc;
        g_unc [b * HW + pix] = uacc;
    }
}

// ---------------- finalize ----------------
__global__ void finalize_pix(float* __restrict__ out) {
    int i = blockIdx.x * blockDim.x + threadIdx.x;
    if (i >= BB * HW) return;
    float d = fmaxf(g_dens[i], 1e-6f);
    float inv = 1.0f / d;
    out[FM_SIZE + i] = g_unc[i] * inv;            // uncertainty / density
    out[FM_SIZE + BB * HW + i] = d;               // clipped density
    g_dens[i] = inv;                              // stash inverse for fm pass
}

__global__ void finalize_fm(float* __restrict__ out) {
    int i = blockIdx.x * blockDim.x + threadIdx.x;
    if (i >= FM_SIZE) return;
    int b = i / (CC * HW);
    int pix = i % HW;
    out[i] *= g_dens[b * HW + pix];
}

// ---------------- launch ----------------
extern "C" void kernel_launch(void* const* d_in, const int* in_sizes, int n_in,
                              void* d_out, int out_size) {
    const float* g      = (const float*)d_in[0];
    const float* intr   = (const float*)d_in[1];
    const float* enc_w1 = (const float*)d_in[2];
    const float* enc_b1 = (const float*)d_in[3];
    const float* enc_w2 = (const float*)d_in[4];
    const float* enc_b2 = (const float*)d_in[5];
    const float* enc_w3 = (const float*)d_in[6];
    const float* enc_b3 = (const float*)d_in[7];
    const float* ft_w1  = (const float*)d_in[8];
    const float* ft_b1  = (const float*)d_in[9];
    const float* ft_w2  = (const float*)d_in[10];
    const float* ft_b2  = (const float*)d_in[11];
    float* out = (float*)d_out;

    float *p_h1, *p_h2, *p_feats, *p_ft1, *p_featsT;
    cudaGetSymbolAddress((void**)&p_h1, g_h1);
    cudaGetSymbolAddress((void**)&p_h2, g_h2);
    cudaGetSymbolAddress((void**)&p_feats, g_feats);
    cudaGetSymbolAddress((void**)&p_ft1, g_ft1);
    cudaGetSymbolAddress((void**)&p_featsT, g_featsT);

    // projection + zero tile counters
    proj_kernel<<<(BN + 255) / 256, 256>>>(g, intr);
    // binning
    bin_kernel<<<(BN + 255) / 256, 256>>>();
    // MLP chain
    gemm_kernel<<<dim3(BN / 64, 64 / 64), 256>>>(g,        enc_w1, enc_b1, p_h1,    BN, 14,  64,  1);
    gemm_kernel<<<dim3(BN / 64, 128 / 64), 256>>>(p_h1,    enc_w2, enc_b2, p_h2,    BN, 64,  128, 1);
    gemm_kernel<<<dim3(BN / 64, 256 / 64), 256>>>(p_h2,    enc_w3, enc_b3, p_feats, BN, 128, 256, 0);
    gemm_kernel<<<dim3(BN / 64, 256 / 64), 256>>>(p_feats, ft_w1,  ft_b1,  p_ft1,   BN, 256, 256, 1);
    gemm_kernel<<<dim3(BN / 64, 256 / 64), 256>>>(p_ft1,   ft_w2,  ft_b2,  p_featsT,BN, 256, 256, 0);
    // render
    render_kernel<<<dim3(NT, 4), 256>>>(out);
    // finalize
    finalize_pix<<<(BB * HW + 255) / 256, 256>>>(out);
    finalize_fm<<<(FM_SIZE + 255) / 256, 256>>>(out);
}